// round 13
// baseline (speedup 1.0000x reference)
#include <cuda_runtime.h>
#include <cuda_bf16.h>
#include <cstdint>

#define U  2048
#define BB 16
#define D  32
#define LOG2E 1.4426950408889634f
#define LN2   0.6931471805599453f

// ---------------- device scratch (no allocations allowed) ----------------
__device__ float g_coldenom[3 * BB * U];          // Σ_i exp(s_ij) per (p,b,j)
__device__ float g_O2[3 * BB * D];
__device__ float g_O1[3 * BB * D];
__device__ __align__(16) float g_CCA[BB * 2 * D];
__device__ unsigned g_ticket;
// packed bf16-split: 0=A*log2e, 1=V, 2=L, 3=V*log2e ; [B,U,64]=[hi|lo] rows
__device__ __align__(16) __nv_bfloat16 g_pack[4][BB * U * 64];

// ---------------- helpers ----------------
__device__ __forceinline__ uint32_t smem_u32(const void* p) {
    uint32_t a;
    asm("{ .reg .u64 t; cvta.to.shared.u64 t, %1; cvt.u32.u64 %0, t; }" : "=r"(a) : "l"(p));
    return a;
}
__device__ __forceinline__ void ldsm4(uint32_t* r, uint32_t addr) {
    asm volatile("ldmatrix.sync.aligned.m8n8.x4.shared.b16 {%0,%1,%2,%3}, [%4];"
                 : "=r"(r[0]), "=r"(r[1]), "=r"(r[2]), "=r"(r[3]) : "r"(addr));
}
__device__ __forceinline__ void mma_bf16(float* c, const uint32_t* a,
                                         uint32_t b0, uint32_t b1) {
    asm volatile(
        "mma.sync.aligned.m16n8k16.row.col.f32.bf16.bf16.f32 "
        "{%0,%1,%2,%3}, {%4,%5,%6,%7}, {%8,%9}, {%0,%1,%2,%3};"
        : "+f"(c[0]), "+f"(c[1]), "+f"(c[2]), "+f"(c[3])
        : "r"(a[0]), "r"(a[1]), "r"(a[2]), "r"(a[3]), "r"(b0), "r"(b1));
}
__device__ __forceinline__ float ex2(float x) {
    float y; asm("ex2.approx.f32 %0, %1;" : "=f"(y) : "f"(x)); return y;
}
__device__ __forceinline__ void cp16(uint32_t dst, const void* src) {
    asm volatile("cp.async.cg.shared.global [%0], [%1], 16;" :: "r"(dst), "l"(src));
}
#define CP_COMMIT() asm volatile("cp.async.commit_group;" ::: "memory")
#define CP_WAIT0()  asm volatile("cp.async.wait_group 0;" ::: "memory")

#define RSTRIDE 72            // SMEM row stride in bf16 (144 B)
#define TILE_B  (128 * 144)   // 18432 B per tile
#define SM_S1 0
#define SM_S2 TILE_B
#define SM_F  (3 * TILE_B)
#define SMEM_TOTAL (SM_F + (128 * 3 + 8 * 32) * 4)

// ---------------- K0: zero accumulators + ticket ----------------
__global__ void k_zero() {
    int i = blockIdx.x * blockDim.x + threadIdx.x;
    if (i < 3 * BB * U) g_coldenom[i] = 0.f;
    if (i < 3 * BB * D) { g_O2[i] = 0.f; g_O1[i] = 0.f; }
    if (i == 0) g_ticket = 0u;
}

// ---------------- Kp: pack fp32 -> bf16 split [hi|lo] (x log2e one side) ----
__global__ void k_pack(const float* __restrict__ A, const float* __restrict__ V,
                       const float* __restrict__ L) {
    int m = blockIdx.y;                               // 0:A*s 1:V 2:L 3:V*s
    const float* src = (m == 0) ? A : (m == 2 ? L : V);
    float scale = (m == 0 || m == 3) ? LOG2E : 1.f;
    int t = blockIdx.x * 256 + threadIdx.x;           // 0 .. 1048575
    float x = src[t] * scale;
    __nv_bfloat16 hi = __float2bfloat16(x);
    __nv_bfloat16 lo = __float2bfloat16(x - __bfloat162float(hi));
    int row = t >> 5, k = t & 31;
    g_pack[m][(size_t)row * 64 + k]      = hi;
    g_pack[m][(size_t)row * 64 + 32 + k] = lo;
}

// ---------------- K1: persistent HMMA main pass (2 CTAs/SM) ----------------
__global__ void __launch_bounds__(256, 2)
k_main(const float* __restrict__ A, const float* __restrict__ V,
       const float* __restrict__ L) {
    extern __shared__ char smem[];
    __shared__ unsigned s_tile;
    float* srow = (float*)(smem + SM_F);              // [128]
    float* se0  = srow + 128;                         // [128]
    float* wbuf = se0 + 128;                          // [128]
    float (*red)[32] = (float (*)[32])(wbuf + 128);   // [8][32]

    const int t = threadIdx.x;
    const int wid = t >> 5, lane = t & 31;
    const int warp_m = wid & 1;
    const int warp_n = wid >> 1;

    const uint32_t sb = smem_u32(smem);
    const uint32_t s1b = sb + SM_S1;
    const uint32_t s2b = sb + SM_S2;

    const int AK[6] = {0, 16, 0, 16, 32, 48};
    const int BK[6] = {0, 16, 32, 48, 0, 16};
    const uint32_t a_rowoff = (uint32_t)(warp_m * 64 + (lane & 15)) * 144;
    const uint32_t a_koff   = (uint32_t)(lane >> 4) * 16;
    const uint32_t b_rowoff = (uint32_t)(warp_n * 32 + ((lane >> 4) << 3) + (lane & 7)) * 144;
    const uint32_t b_koff   = (uint32_t)((lane >> 3) & 1) * 16;

    while (true) {
        if (t == 0) s_tile = atomicAdd(&g_ticket, 1u);
        __syncthreads();
        const unsigned tile = s_tile;
        if (tile >= 768u) break;
        const int p = tile >> 8;                      // /256
        const int rem = tile & 255;
        const int b = rem >> 4, tileI = rem & 15;

        const int m1 = (p == 2) ? 3 : 0;              // f1 (log2e-scaled): A,A,V
        const int m2 = (p == 0) ? 1 : 2;              // f2: V,L,L
        const __nv_bfloat16* F1 = &g_pack[m1][(size_t)(b * U + tileI * 128) * 64];
        const __nv_bfloat16* F2 = &g_pack[m2][(size_t)b * U * 64];
        const float* F1f = ((p == 2) ? V : A) + (size_t)(b * U + tileI * 128) * D;

        if (t < 128) { srow[t] = 0.f; se0[t] = 0.f; }

        // prologue: async-load f1 tile and first f2 tile
#pragma unroll
        for (int q = 0; q < 4; q++) {
            int lin = q * 256 + t;                    // 16B units
            uint32_t so = (uint32_t)(lin >> 3) * 144 + (uint32_t)(lin & 7) * 16;
            cp16(s1b + so, (const uint4*)F1 + lin);
            cp16(s2b + so, (const uint4*)F2 + lin);
        }
        CP_COMMIT();
        CP_WAIT0();
        __syncthreads();

        const int cdbase = (p * BB + b) * U;

        for (int jt = 0; jt < 16; ++jt) {
            const uint32_t cur = (uint32_t)(jt & 1) * TILE_B;
            if (jt + 1 < 16) {                        // prefetch next j-tile
                const uint4* src = (const uint4*)(F2 + (size_t)(jt + 1) * 128 * 64);
                const uint32_t dst = s2b + (TILE_B - cur);
#pragma unroll
                for (int q = 0; q < 4; q++) {
                    int lin = q * 256 + t;
                    cp16(dst + (uint32_t)(lin >> 3) * 144 + (uint32_t)(lin & 7) * 16,
                         src + lin);
                }
                CP_COMMIT();
            }

            float acc[4][4][4];
#pragma unroll
            for (int ma = 0; ma < 4; ma++)
#pragma unroll
                for (int na = 0; na < 4; na++)
#pragma unroll
                    for (int k = 0; k < 4; k++) acc[ma][na][k] = 0.f;

#pragma unroll
            for (int s = 0; s < 6; s++) {
                uint32_t afr[4][4];
#pragma unroll
                for (int ma = 0; ma < 4; ma++)
                    ldsm4(afr[ma], s1b + a_rowoff + (uint32_t)ma * 16 * 144 +
                                   (uint32_t)AK[s] * 2 + a_koff);
                uint32_t bfr[2][4];
#pragma unroll
                for (int q = 0; q < 2; q++)
                    ldsm4(bfr[q], s2b + cur + b_rowoff + (uint32_t)q * 16 * 144 +
                                  (uint32_t)BK[s] * 2 + b_koff);
#pragma unroll
                for (int ma = 0; ma < 4; ma++)
#pragma unroll
                    for (int na = 0; na < 4; na++)
                        mma_bf16(acc[ma][na], afr[ma],
                                 bfr[na >> 1][(na & 1) * 2], bfr[na >> 1][(na & 1) * 2 + 1]);
            }

            // epilogue: exp2 + row/col reductions (logits pre-scaled by log2e)
            float colp[4][2];
#pragma unroll
            for (int na = 0; na < 4; na++) { colp[na][0] = 0.f; colp[na][1] = 0.f; }

#pragma unroll
            for (int ma = 0; ma < 4; ma++) {
                float rp0 = 0.f, rp1 = 0.f;
#pragma unroll
                for (int na = 0; na < 4; na++) {
                    float v0 = ex2(acc[ma][na][0]);
                    float v1 = ex2(acc[ma][na][1]);
                    float v2 = ex2(acc[ma][na][2]);
                    float v3 = ex2(acc[ma][na][3]);
                    rp0 += v0 + v1;  rp1 += v2 + v3;
                    colp[na][0] += v0 + v2;  colp[na][1] += v1 + v3;
                    if (jt == 0 && warp_n == 0 && na == 0 && (lane & 3) == 0) {
                        int r0 = warp_m * 64 + ma * 16 + (lane >> 2);
                        se0[r0]     = v0;
                        se0[r0 + 8] = v2;
                    }
                }
                rp0 += __shfl_xor_sync(0xffffffffu, rp0, 1);
                rp0 += __shfl_xor_sync(0xffffffffu, rp0, 2);
                rp1 += __shfl_xor_sync(0xffffffffu, rp1, 1);
                rp1 += __shfl_xor_sync(0xffffffffu, rp1, 2);
                if ((lane & 3) == 0) {
                    int r0 = warp_m * 64 + ma * 16 + (lane >> 2);
                    atomicAdd(&srow[r0], rp0);
                    atomicAdd(&srow[r0 + 8], rp1);
                }
            }
#pragma unroll
            for (int na = 0; na < 4; na++) {
#pragma unroll
                for (int par = 0; par < 2; par++) {
                    float c = colp[na][par];
                    c += __shfl_xor_sync(0xffffffffu, c, 4);
                    c += __shfl_xor_sync(0xffffffffu, c, 8);
                    c += __shfl_xor_sync(0xffffffffu, c, 16);
                    if ((lane >> 2) == 0)
                        atomicAdd(&g_coldenom[cdbase + jt * 128 + warp_n * 32 +
                                              na * 8 + 2 * lane + par], c);
                }
            }

            CP_WAIT0();                               // next j-tile landed
            __syncthreads();
        }

        if (t < 128) wbuf[t] = se0[t] / srow[t];
        __syncthreads();

        // O2 partial: Σ_i w_i * f1[i][d]  (original fp32 rows, L2-resident)
        {
            int d = t & 31, chk = t >> 5;
            float po = 0.f;
#pragma unroll
            for (int ii = 0; ii < 16; ii++) {
                int i = chk * 16 + ii;
                po += wbuf[i] * F1f[(size_t)i * D + d];
            }
            red[chk][d] = po;
        }
        __syncthreads();
        if (t < 32) {
            float s = 0.f;
#pragma unroll
            for (int c = 0; c < 8; c++) s += red[c][t];
            atomicAdd(&g_O2[(p * BB + b) * D + t], s);
        }
        __syncthreads();                              // wbuf/srow safe to reset
    }
}

// ---------------- K2: O1 partial sums (split 8x over j) ----------------
__global__ void k_stage2(const float* __restrict__ A, const float* __restrict__ V,
                         const float* __restrict__ L) {
    const int p = blockIdx.x, b = blockIdx.y, z = blockIdx.z;
    const float* f1 = (p == 2 ? V : A) + (size_t)b * U * D;
    const float* f2 = (p == 0 ? V : L) + (size_t)b * U * D;
    const int t = threadIdx.x;
    __shared__ float sF10[32];
    __shared__ float sAcc[256][33];
    __shared__ float red[8][32];

    if (t < 32) sF10[t] = f1[t];
    __syncthreads();

    int j = z * 256 + t;
    float f[32];
    const float4* rowp = (const float4*)(f2 + (size_t)j * D);
#pragma unroll
    for (int q = 0; q < 8; q++) *(float4*)&f[q * 4] = rowp[q];
    float dot = 0.f;
#pragma unroll
    for (int k = 0; k < 32; k++) dot += f[k] * sF10[k];
    float w = __expf(dot) / g_coldenom[(p * BB + b) * U + j];
#pragma unroll
    for (int d = 0; d < 32; d++) sAcc[t][d] = w * f[d];
    __syncthreads();
    {
        int d = t & 31, g = t >> 5;
        float s = 0.f;
#pragma unroll
        for (int m = 0; m < 32; m++) s += sAcc[g * 32 + m][d];
        red[g][d] = s;
    }
    __syncthreads();
    if (t < 32) {
        float o1 = 0.f;
#pragma unroll
        for (int g = 0; g < 8; g++) o1 += red[g][t];
        atomicAdd(&g_O1[(p * BB + b) * D + t], o1);
    }
}

// ---------------- K3: Bi assembly + FC head + batch softmax + CCA ----------
__device__ __forceinline__ float fast_tanh(float x) {
    float y;
    asm("tanh.approx.f32 %0, %1;" : "=f"(y) : "f"(x));
    return y;
}

__global__ void k_head(const float* __restrict__ W1, const float* __restrict__ B1,
                       const float* __restrict__ W2, const float* __restrict__ A,
                       const float* __restrict__ V, const float* __restrict__ L) {
    __shared__ float sW1[64 * 65];
    __shared__ float sBi[48 * 64];
    __shared__ float sB1[64], sW2[64];
    __shared__ float sCi[48];
    __shared__ float sMax[3], sSum[3];
    const int t = threadIdx.x, lane = t & 31, w = t >> 5;

    for (int i = t; i < 4096; i += 256) {
        int h = i >> 6, d = i & 63;
        sW1[d * 65 + h] = W1[i];
    }
    for (int i = t; i < 1536; i += 256) {
        int row = i >> 5, d = i & 31;
        int b = row / 3, p = row - b * 3;
        const float* f1 = (p == 2 ? V : A) + (size_t)b * U * D;
        const float* f2 = (p == 0 ? V : L) + (size_t)b * U * D;
        int pb = (p * BB + b) * D;
        sBi[row * 64 + d]      = g_O1[pb + d] * f1[d];
        sBi[row * 64 + 32 + d] = g_O2[pb + d] * f2[d];
    }
    if (t < 64) { sB1[t] = B1[t]; sW2[t] = W2[t]; }
    __syncthreads();

    for (int rr = 0; rr < 6; rr++) {
        int row = rr * 8 + w;
        float c = 0.f;
#pragma unroll
        for (int hh = 0; hh < 2; hh++) {
            int hid = hh * 32 + lane;
            const float* bi = &sBi[row * 64];
            float a0 = sB1[hid], a1 = 0.f, a2 = 0.f, a3 = 0.f;
#pragma unroll
            for (int dd = 0; dd < 64; dd += 4) {
                a0 += sW1[(dd + 0) * 65 + hid] * bi[dd + 0];
                a1 += sW1[(dd + 1) * 65 + hid] * bi[dd + 1];
                a2 += sW1[(dd + 2) * 65 + hid] * bi[dd + 2];
                a3 += sW1[(dd + 3) * 65 + hid] * bi[dd + 3];
            }
            c += fast_tanh((a0 + a1) + (a2 + a3)) * sW2[hid];
        }
#pragma unroll
        for (int o = 16; o; o >>= 1) c += __shfl_xor_sync(0xffffffffu, c, o);
        if (lane == 0) sCi[row] = c;
    }
    __syncthreads();
    if (t < 3) {
        float m = -1e30f;
        for (int b = 0; b < BB; b++) m = fmaxf(m, sCi[b * 3 + t]);
        float s = 0.f;
        for (int b = 0; b < BB; b++) s += __expf(sCi[b * 3 + t] - m);
        sMax[t] = m; sSum[t] = s;
    }
    __syncthreads();
    for (int it = 0; it < 4; it++) {
        int idx = it * 256 + t;
        int b = idx >> 6, dd = idx & 63;
        float o = 0.f;
#pragma unroll
        for (int k = 0; k < 3; k++) {
            float al = __expf(sCi[b * 3 + k] - sMax[k]) / sSum[k];
            o += al * sBi[(b * 3 + k) * 64 + dd];
        }
        g_CCA[idx] = o;
    }
}

// ---------------- K4: broadcast CCA_i across U ----------------
__global__ void k_bcast(float4* __restrict__ out) {
    int g = blockIdx.x * 256 + threadIdx.x;
    int b = g >> 15;
    int d4 = g & 15;
    out[g] = *(const float4*)&g_CCA[(b * 16 + d4) * 4];
}

// ---------------- launcher ----------------
extern "C" void kernel_launch(void* const* d_in, const int* in_sizes, int n_in,
                              void* d_out, int out_size) {
    (void)in_sizes; (void)n_in; (void)out_size;
    const float* A  = (const float*)d_in[0];
    const float* V  = (const float*)d_in[1];
    const float* L  = (const float*)d_in[2];
    const float* W1 = (const float*)d_in[3];
    const float* B1 = (const float*)d_in[4];
    const float* W2 = (const float*)d_in[5];

    static int smem_set = 0;
    if (!smem_set) {
        cudaFuncSetAttribute(k_main, cudaFuncAttributeMaxDynamicSharedMemorySize,
                             SMEM_TOTAL);
        smem_set = 1;
    }

    k_zero<<<384, 256>>>();
    k_pack<<<dim3(4096, 4), 256>>>(A, V, L);
    k_main<<<304, 256, SMEM_TOTAL>>>(A, V, L);
    k_stage2<<<dim3(3, 16, 8), 256>>>(A, V, L);
    k_head<<<1, 256>>>(W1, B1, W2, A, V, L);
    k_bcast<<<2048, 256>>>((float4*)d_out);
}

// round 17
// speedup vs baseline: 1.4901x; 1.4901x over previous
#include <cuda_runtime.h>
#include <cuda_bf16.h>
#include <cstdint>

#define U  2048
#define BB 16
#define D  32
#define LOG2E 1.4426950408889634f
#define LN2   0.6931471805599453f

// ---------------- device scratch (no allocations allowed) ----------------
__device__ float g_coldenom[3 * BB * U];          // Σ_i exp(s_ij) per (p,b,j)
__device__ float g_O2[3 * BB * D];
__device__ float g_O1[3 * BB * D];
__device__ __align__(16) float g_CCA[BB * 2 * D];
// packed bf16-split: 0=A*log2e, 1=V, 2=L, 3=V*log2e ; [B,U,64]=[hi|lo] rows
__device__ __align__(16) __nv_bfloat16 g_pack[4][BB * U * 64];

// ---------------- helpers ----------------
__device__ __forceinline__ uint32_t smem_u32(const void* p) {
    uint32_t a;
    asm("{ .reg .u64 t; cvta.to.shared.u64 t, %1; cvt.u32.u64 %0, t; }" : "=r"(a) : "l"(p));
    return a;
}
__device__ __forceinline__ void ldsm4(uint32_t* r, uint32_t addr) {
    asm volatile("ldmatrix.sync.aligned.m8n8.x4.shared.b16 {%0,%1,%2,%3}, [%4];"
                 : "=r"(r[0]), "=r"(r[1]), "=r"(r[2]), "=r"(r[3]) : "r"(addr));
}
__device__ __forceinline__ void mma_bf16(float* c, const uint32_t* a,
                                         uint32_t b0, uint32_t b1) {
    asm volatile(
        "mma.sync.aligned.m16n8k16.row.col.f32.bf16.bf16.f32 "
        "{%0,%1,%2,%3}, {%4,%5,%6,%7}, {%8,%9}, {%0,%1,%2,%3};"
        : "+f"(c[0]), "+f"(c[1]), "+f"(c[2]), "+f"(c[3])
        : "r"(a[0]), "r"(a[1]), "r"(a[2]), "r"(a[3]), "r"(b0), "r"(b1));
}
__device__ __forceinline__ float ex2(float x) {
    float y; asm("ex2.approx.f32 %0, %1;" : "=f"(y) : "f"(x)); return y;
}
__device__ __forceinline__ void cp16(uint32_t dst, const void* src) {
    asm volatile("cp.async.cg.shared.global [%0], [%1], 16;" :: "r"(dst), "l"(src));
}
#define CP_COMMIT() asm volatile("cp.async.commit_group;" ::: "memory")
#define CP_WAIT0()  asm volatile("cp.async.wait_group 0;" ::: "memory")

#define RSTRIDE 72            // SMEM row stride in bf16 (144 B)
#define TILE_B  (128 * 144)   // 18432 B per tile
#define SM_S1 0
#define SM_S2 TILE_B
#define SM_F  (3 * TILE_B)
#define SMEM_TOTAL (SM_F + (128 * 3 + 8 * 32) * 4)

// ---------------- K0: zero accumulators ----------------
__global__ void k_zero() {
    int i = blockIdx.x * blockDim.x + threadIdx.x;
    if (i < 3 * BB * U) g_coldenom[i] = 0.f;
    if (i < 3 * BB * D) { g_O2[i] = 0.f; g_O1[i] = 0.f; }
}

// ---------------- Kp: pack fp32 -> bf16 split [hi|lo] (x log2e one side) ----
__global__ void k_pack(const float* __restrict__ A, const float* __restrict__ V,
                       const float* __restrict__ L) {
    int m = blockIdx.y;                               // 0:A*s 1:V 2:L 3:V*s
    const float* src = (m == 0) ? A : (m == 2 ? L : V);
    float scale = (m == 0 || m == 3) ? LOG2E : 1.f;
    int t = blockIdx.x * 256 + threadIdx.x;           // 0 .. 1048575
    float x = src[t] * scale;
    __nv_bfloat16 hi = __float2bfloat16(x);
    __nv_bfloat16 lo = __float2bfloat16(x - __bfloat162float(hi));
    int row = t >> 5, k = t & 31;
    g_pack[m][(size_t)row * 64 + k]      = hi;
    g_pack[m][(size_t)row * 64 + 32 + k] = lo;
}

// ---------------- K1: HMMA main pass (R8-verified loop structure) ----------
__global__ void __launch_bounds__(256, 2)
k_main() {
    extern __shared__ char smem[];
    float* srow = (float*)(smem + SM_F);              // [128]
    float* se0  = srow + 128;                         // [128]
    float* wbuf = se0 + 128;                          // [128]
    float (*red)[32] = (float (*)[32])(wbuf + 128);   // [8][32]

    const int tileI = blockIdx.x, b = blockIdx.y, p = blockIdx.z;
    const int m1 = (p == 2) ? 3 : 0;                  // f1 (log2e-scaled): A,A,V
    const int m2 = (p == 0) ? 1 : 2;                  // f2: V,L,L
    const __nv_bfloat16* F1 = &g_pack[m1][(size_t)(b * U + tileI * 128) * 64];
    const __nv_bfloat16* F2 = &g_pack[m2][(size_t)b * U * 64];

    const int t = threadIdx.x;
    const int wid = t >> 5, lane = t & 31;
    const int warp_m = wid & 1;
    const int warp_n = wid >> 1;

    const uint32_t sb = smem_u32(smem);
    const uint32_t s1b = sb + SM_S1;
    const uint32_t s2b = sb + SM_S2;

    if (t < 128) { srow[t] = 0.f; se0[t] = 0.f; }

    // prologue: async-load f1 tile and first f2 tile
#pragma unroll
    for (int q = 0; q < 4; q++) {
        int lin = q * 256 + t;                        // 16B units
        uint32_t so = (uint32_t)(lin >> 3) * 144 + (uint32_t)(lin & 7) * 16;
        cp16(s1b + so, (const uint4*)F1 + lin);
        cp16(s2b + so, (const uint4*)F2 + lin);
    }
    CP_COMMIT();
    CP_WAIT0();
    __syncthreads();

    const int AK[6] = {0, 16, 0, 16, 32, 48};
    const int BK[6] = {0, 16, 32, 48, 0, 16};

    const uint32_t a_rowoff = (uint32_t)(warp_m * 64 + (lane & 15)) * 144;
    const uint32_t a_koff   = (uint32_t)(lane >> 4) * 16;
    const uint32_t b_rowoff = (uint32_t)(warp_n * 32 + ((lane >> 4) << 3) + (lane & 7)) * 144;
    const uint32_t b_koff   = (uint32_t)((lane >> 3) & 1) * 16;
    const int cdbase = (p * BB + b) * U;

    for (int jt = 0; jt < 16; ++jt) {
        const uint32_t cur = (uint32_t)(jt & 1) * TILE_B;
        if (jt + 1 < 16) {                            // prefetch next j-tile
            const uint4* src = (const uint4*)(F2 + (size_t)(jt + 1) * 128 * 64);
            const uint32_t dst = s2b + (TILE_B - cur);
#pragma unroll
            for (int q = 0; q < 4; q++) {
                int lin = q * 256 + t;
                cp16(dst + (uint32_t)(lin >> 3) * 144 + (uint32_t)(lin & 7) * 16,
                     src + lin);
            }
            CP_COMMIT();
        }

        float acc[4][4][4];
#pragma unroll
        for (int ma = 0; ma < 4; ma++)
#pragma unroll
            for (int na = 0; na < 4; na++)
#pragma unroll
                for (int k = 0; k < 4; k++) acc[ma][na][k] = 0.f;

#pragma unroll
        for (int s = 0; s < 6; s++) {
            uint32_t afr[4][4];
#pragma unroll
            for (int ma = 0; ma < 4; ma++)
                ldsm4(afr[ma], s1b + a_rowoff + (uint32_t)ma * 16 * 144 +
                               (uint32_t)AK[s] * 2 + a_koff);
            uint32_t bfr[2][4];
#pragma unroll
            for (int q = 0; q < 2; q++)
                ldsm4(bfr[q], s2b + cur + b_rowoff + (uint32_t)q * 16 * 144 +
                              (uint32_t)BK[s] * 2 + b_koff);
#pragma unroll
            for (int ma = 0; ma < 4; ma++)
#pragma unroll
                for (int na = 0; na < 4; na++)
                    mma_bf16(acc[ma][na], afr[ma],
                             bfr[na >> 1][(na & 1) * 2], bfr[na >> 1][(na & 1) * 2 + 1]);
        }

        // epilogue: exp2 + row/col reductions (logits pre-scaled by log2e)
        float colp[4][2];
#pragma unroll
        for (int na = 0; na < 4; na++) { colp[na][0] = 0.f; colp[na][1] = 0.f; }

#pragma unroll
        for (int ma = 0; ma < 4; ma++) {
            float rp0 = 0.f, rp1 = 0.f;
#pragma unroll
            for (int na = 0; na < 4; na++) {
                float v0 = ex2(acc[ma][na][0]);
                float v1 = ex2(acc[ma][na][1]);
                float v2 = ex2(acc[ma][na][2]);
                float v3 = ex2(acc[ma][na][3]);
                rp0 += v0 + v1;  rp1 += v2 + v3;
                colp[na][0] += v0 + v2;  colp[na][1] += v1 + v3;
                if (jt == 0 && warp_n == 0 && na == 0 && (lane & 3) == 0) {
                    int r0 = warp_m * 64 + ma * 16 + (lane >> 2);
                    se0[r0]     = v0;
                    se0[r0 + 8] = v2;
                }
            }
            rp0 += __shfl_xor_sync(0xffffffffu, rp0, 1);
            rp0 += __shfl_xor_sync(0xffffffffu, rp0, 2);
            rp1 += __shfl_xor_sync(0xffffffffu, rp1, 1);
            rp1 += __shfl_xor_sync(0xffffffffu, rp1, 2);
            if ((lane & 3) == 0) {
                int r0 = warp_m * 64 + ma * 16 + (lane >> 2);
                atomicAdd(&srow[r0], rp0);
                atomicAdd(&srow[r0 + 8], rp1);
            }
        }
#pragma unroll
        for (int na = 0; na < 4; na++) {
#pragma unroll
            for (int par = 0; par < 2; par++) {
                float c = colp[na][par];
                c += __shfl_xor_sync(0xffffffffu, c, 4);
                c += __shfl_xor_sync(0xffffffffu, c, 8);
                c += __shfl_xor_sync(0xffffffffu, c, 16);
                if ((lane >> 2) == 0)
                    atomicAdd(&g_coldenom[cdbase + jt * 128 + warp_n * 32 +
                                          na * 8 + 2 * lane + par], c);
            }
        }

        CP_WAIT0();                                   // next j-tile landed
        __syncthreads();
    }

    if (t < 128) wbuf[t] = se0[t] / srow[t];
    __syncthreads();

    // O2 partial: Σ_i w_i * f1[i][d]  (s1 holds log2e-scaled f1 -> fix with LN2)
    {
        int d = t & 31, chk = t >> 5;
        const __nv_bfloat16* s1h = (const __nv_bfloat16*)smem;
        float po = 0.f;
#pragma unroll
        for (int ii = 0; ii < 16; ii++) {
            int i = chk * 16 + ii;
            float f = __bfloat162float(s1h[i * RSTRIDE + d]) +
                      __bfloat162float(s1h[i * RSTRIDE + 32 + d]);
            po += wbuf[i] * f;
        }
        red[chk][d] = po;
    }
    __syncthreads();
    if (t < 32) {
        float s = 0.f;
#pragma unroll
        for (int c = 0; c < 8; c++) s += red[c][t];
        atomicAdd(&g_O2[(p * BB + b) * D + t], s * LN2);
    }
}

// ---------------- K2: O1 partial sums (split 8x over j) ----------------
__global__ void k_stage2(const float* __restrict__ A, const float* __restrict__ V,
                         const float* __restrict__ L) {
    const int p = blockIdx.x, b = blockIdx.y, z = blockIdx.z;
    const float* f1 = (p == 2 ? V : A) + (size_t)b * U * D;
    const float* f2 = (p == 0 ? V : L) + (size_t)b * U * D;
    const int t = threadIdx.x;
    __shared__ float sF10[32];
    __shared__ float sAcc[256][33];
    __shared__ float red[8][32];

    if (t < 32) sF10[t] = f1[t];
    __syncthreads();

    int j = z * 256 + t;
    float f[32];
    const float4* rowp = (const float4*)(f2 + (size_t)j * D);
#pragma unroll
    for (int q = 0; q < 8; q++) *(float4*)&f[q * 4] = rowp[q];
    float dot = 0.f;
#pragma unroll
    for (int k = 0; k < 32; k++) dot += f[k] * sF10[k];
    float w = __expf(dot) / g_coldenom[(p * BB + b) * U + j];
#pragma unroll
    for (int d = 0; d < 32; d++) sAcc[t][d] = w * f[d];
    __syncthreads();
    {
        int d = t & 31, g = t >> 5;
        float s = 0.f;
#pragma unroll
        for (int m = 0; m < 32; m++) s += sAcc[g * 32 + m][d];
        red[g][d] = s;
    }
    __syncthreads();
    if (t < 32) {
        float o1 = 0.f;
#pragma unroll
        for (int g = 0; g < 8; g++) o1 += red[g][t];
        atomicAdd(&g_O1[(p * BB + b) * D + t], o1);
    }
}

// ---------------- K3: Bi assembly + FC head + batch softmax + CCA ----------
__device__ __forceinline__ float fast_tanh(float x) {
    float y;
    asm("tanh.approx.f32 %0, %1;" : "=f"(y) : "f"(x));
    return y;
}

__global__ void k_head(const float* __restrict__ W1, const float* __restrict__ B1,
                       const float* __restrict__ W2, const float* __restrict__ A,
                       const float* __restrict__ V, const float* __restrict__ L) {
    __shared__ float sW1[64 * 65];
    __shared__ float sBi[48 * 64];
    __shared__ float sB1[64], sW2[64];
    __shared__ float sCi[48];
    __shared__ float sMax[3], sSum[3];
    const int t = threadIdx.x, lane = t & 31, w = t >> 5;

    for (int i = t; i < 4096; i += 256) {
        int h = i >> 6, d = i & 63;
        sW1[d * 65 + h] = W1[i];
    }
    for (int i = t; i < 1536; i += 256) {
        int row = i >> 5, d = i & 31;
        int b = row / 3, p = row - b * 3;
        const float* f1 = (p == 2 ? V : A) + (size_t)b * U * D;
        const float* f2 = (p == 0 ? V : L) + (size_t)b * U * D;
        int pb = (p * BB + b) * D;
        sBi[row * 64 + d]      = g_O1[pb + d] * f1[d];
        sBi[row * 64 + 32 + d] = g_O2[pb + d] * f2[d];
    }
    if (t < 64) { sB1[t] = B1[t]; sW2[t] = W2[t]; }
    __syncthreads();

    for (int rr = 0; rr < 6; rr++) {
        int row = rr * 8 + w;
        float c = 0.f;
#pragma unroll
        for (int hh = 0; hh < 2; hh++) {
            int hid = hh * 32 + lane;
            const float* bi = &sBi[row * 64];
            float a0 = sB1[hid], a1 = 0.f, a2 = 0.f, a3 = 0.f;
#pragma unroll
            for (int dd = 0; dd < 64; dd += 4) {
                a0 += sW1[(dd + 0) * 65 + hid] * bi[dd + 0];
                a1 += sW1[(dd + 1) * 65 + hid] * bi[dd + 1];
                a2 += sW1[(dd + 2) * 65 + hid] * bi[dd + 2];
                a3 += sW1[(dd + 3) * 65 + hid] * bi[dd + 3];
            }
            c += fast_tanh((a0 + a1) + (a2 + a3)) * sW2[hid];
        }
#pragma unroll
        for (int o = 16; o; o >>= 1) c += __shfl_xor_sync(0xffffffffu, c, o);
        if (lane == 0) sCi[row] = c;
    }
    __syncthreads();
    if (t < 3) {
        float m = -1e30f;
        for (int b = 0; b < BB; b++) m = fmaxf(m, sCi[b * 3 + t]);
        float s = 0.f;
        for (int b = 0; b < BB; b++) s += __expf(sCi[b * 3 + t] - m);
        sMax[t] = m; sSum[t] = s;
    }
    __syncthreads();
    for (int it = 0; it < 4; it++) {
        int idx = it * 256 + t;
        int b = idx >> 6, dd = idx & 63;
        float o = 0.f;
#pragma unroll
        for (int k = 0; k < 3; k++) {
            float al = __expf(sCi[b * 3 + k] - sMax[k]) / sSum[k];
            o += al * sBi[(b * 3 + k) * 64 + dd];
        }
        g_CCA[idx] = o;
    }
}

// ---------------- K4: broadcast CCA_i across U ----------------
__global__ void k_bcast(float4* __restrict__ out) {
    int g = blockIdx.x * 256 + threadIdx.x;
    int b = g >> 15;
    int d4 = g & 15;
    out[g] = *(const float4*)&g_CCA[(b * 16 + d4) * 4];
}

// ---------------- launcher ----------------
extern "C" void kernel_launch(void* const* d_in, const int* in_sizes, int n_in,
                              void* d_out, int out_size) {
    (void)in_sizes; (void)n_in; (void)out_size;
    const float* A  = (const float*)d_in[0];
    const float* V  = (const float*)d_in[1];
    const float* L  = (const float*)d_in[2];
    const float* W1 = (const float*)d_in[3];
    const float* B1 = (const float*)d_in[4];
    const float* W2 = (const float*)d_in[5];

    static int smem_set = 0;
    if (!smem_set) {
        cudaFuncSetAttribute(k_main, cudaFuncAttributeMaxDynamicSharedMemorySize,
                             SMEM_TOTAL);
        smem_set = 1;
    }

    k_zero<<<384, 256>>>();
    k_pack<<<dim3(4096, 4), 256>>>(A, V, L);
    k_main<<<dim3(16, 16, 3), 256, SMEM_TOTAL>>>();
    k_stage2<<<dim3(3, 16, 8), 256>>>(A, V, L);
    k_head<<<1, 256>>>(W1, B1, W2, A, V, L);
    k_bcast<<<2048, 256>>>((float4*)d_out);
}